// round 1
// baseline (speedup 1.0000x reference)
#include <cuda_runtime.h>
#include <math.h>

#define TT   4096
#define HIDN 4096
#define HH   32
#define DD   64
#define PP   2048

__device__ float d_qpre[(size_t)TT * PP];
__device__ float d_kpre[(size_t)TT * PP];
__device__ float d_vpre[(size_t)TT * PP];
__device__ float d_qn[(size_t)TT * PP];
__device__ float d_kn[(size_t)TT * PP];
__device__ float d_vn[(size_t)TT * PP];
__device__ float d_g[(size_t)TT * PP];
__device__ float d_g2[(size_t)TT * PP];
__device__ float d_ob[(size_t)TT * PP];
__device__ float d_beta[(size_t)TT * HH];
__device__ float d_fa[(size_t)TT * DD];
__device__ float d_ga[(size_t)TT * DD];

__global__ __launch_bounds__(256, 2)
void gemm128(const float* __restrict__ A, const float* __restrict__ B,
             float* __restrict__ C, int M, int N, int K) {
    __shared__ __align__(16) float As[16][128];
    __shared__ __align__(16) float Bs[16][128];
    const int tid = threadIdx.x;
    const int bm = blockIdx.y * 128;
    const int bn = blockIdx.x * 128;
    const int aRow = tid >> 2;
    const int aCol = (tid & 3) << 2;
    const int bRow = tid >> 5;
    const int bCol = (tid & 31) << 2;
    const int ty = (tid >> 4) << 3;
    const int tx = (tid & 15) << 3;
    float acc[8][8];
#pragma unroll
    for (int i = 0; i < 8; i++)
#pragma unroll
        for (int j = 0; j < 8; j++) acc[i][j] = 0.f;

    for (int k0 = 0; k0 < K; k0 += 16) {
        float4 a0 = *(const float4*)(A + (size_t)(bm + aRow) * K + k0 + aCol);
        float4 a1 = *(const float4*)(A + (size_t)(bm + aRow + 64) * K + k0 + aCol);
        float4 b0 = *(const float4*)(B + (size_t)(k0 + bRow) * N + bn + bCol);
        float4 b1 = *(const float4*)(B + (size_t)(k0 + bRow + 8) * N + bn + bCol);
        As[aCol + 0][aRow] = a0.x; As[aCol + 1][aRow] = a0.y;
        As[aCol + 2][aRow] = a0.z; As[aCol + 3][aRow] = a0.w;
        As[aCol + 0][aRow + 64] = a1.x; As[aCol + 1][aRow + 64] = a1.y;
        As[aCol + 2][aRow + 64] = a1.z; As[aCol + 3][aRow + 64] = a1.w;
        *(float4*)(&Bs[bRow][bCol]) = b0;
        *(float4*)(&Bs[bRow + 8][bCol]) = b1;
        __syncthreads();
#pragma unroll
        for (int kk = 0; kk < 16; kk++) {
            float ra[8], rb[8];
            *(float4*)(ra)     = *(const float4*)(&As[kk][ty]);
            *(float4*)(ra + 4) = *(const float4*)(&As[kk][ty + 4]);
            *(float4*)(rb)     = *(const float4*)(&Bs[kk][tx]);
            *(float4*)(rb + 4) = *(const float4*)(&Bs[kk][tx + 4]);
#pragma unroll
            for (int i = 0; i < 8; i++)
#pragma unroll
                for (int j = 0; j < 8; j++)
                    acc[i][j] += ra[i] * rb[j];
        }
        __syncthreads();
    }
#pragma unroll
    for (int i = 0; i < 8; i++) {
        float4* crow = (float4*)(C + (size_t)(bm + ty + i) * N + bn + tx);
        crow[0] = make_float4(acc[i][0], acc[i][1], acc[i][2], acc[i][3]);
        crow[1] = make_float4(acc[i][4], acc[i][5], acc[i][6], acc[i][7]);
    }
}

__global__ __launch_bounds__(256)
void gemm_small(const float* __restrict__ A, const float* __restrict__ B,
                float* __restrict__ C, int M, int N, int K, int act) {
    __shared__ __align__(16) float sA[16][64];
    __shared__ float sB[64][64];
    const int tid = threadIdx.x;
    const int m0 = blockIdx.x << 4;
    const int na = (16 * N) >> 8;
    int rows[4], cols[4];
#pragma unroll
    for (int a = 0; a < 4; a++) {
        int e = tid + (a << 8);
        if (e >= 16 * N) e = 0;
        rows[a] = e / N; cols[a] = e % N;
    }
    float acc[4] = {0.f, 0.f, 0.f, 0.f};
    const int ar = tid >> 4, ac = (tid & 15) << 2;
    for (int k0 = 0; k0 < K; k0 += 64) {
        *(float4*)(&sA[ar][ac]) = *(const float4*)(A + (size_t)(m0 + ar) * K + k0 + ac);
        for (int i = tid; i < 64 * N; i += 256)
            sB[i / N][i % N] = B[(size_t)(k0 + i / N) * N + (i % N)];
        __syncthreads();
#pragma unroll 8
        for (int kk = 0; kk < 64; kk++) {
#pragma unroll
            for (int a = 0; a < 4; a++)
                acc[a] += sA[rows[a]][kk] * sB[kk][cols[a]];
        }
        __syncthreads();
    }
#pragma unroll
    for (int a = 0; a < 4; a++) {
        if (a < na) {
            float v = acc[a];
            if (act == 1) v = 1.f / (1.f + expf(-v));
            C[(size_t)(m0 + rows[a]) * N + cols[a]] = v;
        }
    }
}

__global__ void conv_silu(const float* __restrict__ in, const float* __restrict__ w,
                          float* __restrict__ out) {
    int idx = blockIdx.x * 256 + threadIdx.x;
    int t = idx >> 11;
    int p = idx & (PP - 1);
    float4 wv = *(const float4*)(w + p * 4);
    float acc = in[idx] * wv.w;
    if (t >= 1) acc += in[idx - PP] * wv.z;
    if (t >= 2) acc += in[idx - 2 * PP] * wv.y;
    if (t >= 3) acc += in[idx - 3 * PP] * wv.x;
    out[idx] = acc / (1.f + expf(-acc));
}

__global__ void l2norm_kernel(float* __restrict__ x, float scale) {
    int r = blockIdx.x * 8 + (threadIdx.x >> 5);
    int lane = threadIdx.x & 31;
    size_t base = (size_t)r * 64 + lane * 2;
    float2 v = *(float2*)(x + base);
    float ss = v.x * v.x + v.y * v.y;
#pragma unroll
    for (int m = 16; m; m >>= 1) ss += __shfl_xor_sync(0xffffffffu, ss, m);
    float rn = rsqrtf(ss + 1e-6f) * scale;
    v.x *= rn; v.y *= rn;
    *(float2*)(x + base) = v;
}

__global__ void gate_kernel(float* __restrict__ g, const float* __restrict__ dt_bias,
                            const float* __restrict__ A_log) {
    int idx = blockIdx.x * 256 + threadIdx.x;
    int p = idx & (PP - 1);
    int h = p >> 6;
    float val = g[idx] + dt_bias[p];
    float sp = (val > 20.f) ? val : log1pf(expf(val));
    g[idx] = -expf(A_log[h]) * sp;
}

__global__ __launch_bounds__(256)
void scan_kernel(const float* __restrict__ q, const float* __restrict__ k,
                 const float* __restrict__ v, const float* __restrict__ g,
                 const float* __restrict__ beta, float* __restrict__ o) {
    const int h = blockIdx.x;
    const int cg = blockIdx.y;
    const int tid = threadIdx.x;
    const int dvl = tid >> 4;
    const int kp = tid & 15;
    const int dk0 = kp << 2;
    const int dv = (cg << 4) + dvl;

    float S0 = 0.f, S1 = 0.f, S2 = 0.f, S3 = 0.f;
    __shared__ __align__(16) float sk[64];
    __shared__ __align__(16) float sq[64];
    __shared__ __align__(16) float seg[64];
    __shared__ float sv[16];
    __shared__ float sbeta;

    for (int t = 0; t < TT; t++) {
        const int base = (t * HH + h) * DD;
        if (tid < 64) {
            sk[tid] = k[base + tid];
            sq[tid] = q[base + tid];
            seg[tid] = expf(g[base + tid]);
        } else if (tid < 80) {
            sv[tid - 64] = v[base + (cg << 4) + (tid - 64)];
        } else if (tid == 80) {
            sbeta = beta[t * HH + h];
        }
        __syncthreads();
        float4 kv = *(const float4*)(sk + dk0);
        float4 ev = *(const float4*)(seg + dk0);
        S0 *= ev.x; S1 *= ev.y; S2 *= ev.z; S3 *= ev.w;
        float vp = kv.x * S0 + kv.y * S1 + kv.z * S2 + kv.w * S3;
        vp += __shfl_xor_sync(0xffffffffu, vp, 1);
        vp += __shfl_xor_sync(0xffffffffu, vp, 2);
        vp += __shfl_xor_sync(0xffffffffu, vp, 4);
        vp += __shfl_xor_sync(0xffffffffu, vp, 8);
        const float delta = (sv[dvl] - vp) * sbeta;
        S0 += kv.x * delta; S1 += kv.y * delta;
        S2 += kv.z * delta; S3 += kv.w * delta;
        float4 qv = *(const float4*)(sq + dk0);
        float op = qv.x * S0 + qv.y * S1 + qv.z * S2 + qv.w * S3;
        op += __shfl_xor_sync(0xffffffffu, op, 1);
        op += __shfl_xor_sync(0xffffffffu, op, 2);
        op += __shfl_xor_sync(0xffffffffu, op, 4);
        op += __shfl_xor_sync(0xffffffffu, op, 8);
        if (kp == 0) o[base + dv] = op;
        __syncthreads();
    }
}

__global__ void rmsnorm_gate(float* __restrict__ o, const float* __restrict__ g2,
                             const float* __restrict__ w) {
    int r = blockIdx.x * 8 + (threadIdx.x >> 5);
    int lane = threadIdx.x & 31;
    size_t base = (size_t)r * 64 + lane * 2;
    float2 ov = *(float2*)(o + base);
    float ss = ov.x * ov.x + ov.y * ov.y;
#pragma unroll
    for (int m = 16; m; m >>= 1) ss += __shfl_xor_sync(0xffffffffu, ss, m);
    float rms = rsqrtf(ss * (1.f / 64.f) + 1e-5f);
    float2 gv = *(const float2*)(g2 + base);
    float w0 = w[lane * 2], w1 = w[lane * 2 + 1];
    ov.x = ov.x * rms * w0 / (1.f + expf(-gv.x));
    ov.y = ov.y * rms * w1 / (1.f + expf(-gv.y));
    *(float2*)(o + base) = ov;
}

extern "C" void kernel_launch(void* const* d_in, const int* in_sizes, int n_in,
                              void* d_out, int out_size) {
    (void)in_sizes; (void)n_in; (void)out_size;
    const float* x       = (const float*)d_in[0];
    const float* Wq      = (const float*)d_in[1];
    const float* Wk      = (const float*)d_in[2];
    const float* Wv      = (const float*)d_in[3];
    const float* Wb      = (const float*)d_in[4];
    const float* Wfa     = (const float*)d_in[5];
    const float* Wfb     = (const float*)d_in[6];
    const float* dt_bias = (const float*)d_in[7];
    const float* A_log   = (const float*)d_in[8];
    const float* Wga     = (const float*)d_in[9];
    const float* Wgb     = (const float*)d_in[10];
    const float* conv_q  = (const float*)d_in[11];
    const float* conv_k  = (const float*)d_in[12];
    const float* conv_v  = (const float*)d_in[13];
    const float* o_w     = (const float*)d_in[14];
    const float* Wo      = (const float*)d_in[15 - 1 + 1];  // placeholder, fixed below
    Wo = (const float*)d_in[15];  // positions is index 15? NO — see metadata note below
    float* out = (float*)d_out;

    // metadata order: 0 hidden_states, 1 Wq, 2 Wk, 3 Wv, 4 Wb, 5 Wfa, 6 Wfb,
    // 7 dt_bias, 8 A_log, 9 Wga, 10 Wgb, 11 conv_q, 12 conv_k, 13 conv_v,
    // 14 o_norm_weight, 15 Wo, 16 positions
    Wo = (const float*)d_in[15];

    float *qpre, *kpre, *vpre, *qn, *kn, *vn, *g, *g2, *ob, *beta, *fa, *ga;
    cudaGetSymbolAddress((void**)&qpre, d_qpre);
    cudaGetSymbolAddress((void**)&kpre, d_kpre);
    cudaGetSymbolAddress((void**)&vpre, d_vpre);
    cudaGetSymbolAddress((void**)&qn, d_qn);
    cudaGetSymbolAddress((void**)&kn, d_kn);
    cudaGetSymbolAddress((void**)&vn, d_vn);
    cudaGetSymbolAddress((void**)&g, d_g);
    cudaGetSymbolAddress((void**)&g2, d_g2);
    cudaGetSymbolAddress((void**)&ob, d_ob);
    cudaGetSymbolAddress((void**)&beta, d_beta);
    cudaGetSymbolAddress((void**)&fa, d_fa);
    cudaGetSymbolAddress((void**)&ga, d_ga);

    dim3 blk(256);
    dim3 gQKV(PP / 128, TT / 128);
    dim3 gOut(HIDN / 128, TT / 128);

    gemm128<<<gQKV, blk>>>(x, Wq, qpre, TT, PP, HIDN);
    gemm128<<<gQKV, blk>>>(x, Wk, kpre, TT, PP, HIDN);
    gemm128<<<gQKV, blk>>>(x, Wv, vpre, TT, PP, HIDN);
    gemm_small<<<TT / 16, 256>>>(x, Wb,  beta, TT, HH, HIDN, 1);
    gemm_small<<<TT / 16, 256>>>(x, Wfa, fa,   TT, DD, HIDN, 0);
    gemm_small<<<TT / 16, 256>>>(x, Wga, ga,   TT, DD, HIDN, 0);
    gemm128<<<gQKV, blk>>>(fa, Wfb, g,  TT, PP, DD);
    gemm128<<<gQKV, blk>>>(ga, Wgb, g2, TT, PP, DD);

    int ne = TT * PP;
    conv_silu<<<ne / 256, 256>>>(qpre, conv_q, qn);
    conv_silu<<<ne / 256, 256>>>(kpre, conv_k, kn);
    conv_silu<<<ne / 256, 256>>>(vpre, conv_v, vn);

    l2norm_kernel<<<TT * HH / 8, 256>>>(qn, 0.125f);
    l2norm_kernel<<<TT * HH / 8, 256>>>(kn, 1.0f);

    gate_kernel<<<ne / 256, 256>>>(g, dt_bias, A_log);

    scan_kernel<<<dim3(HH, 4), 256>>>(qn, kn, vn, g, beta, ob);

    rmsnorm_gate<<<TT * HH / 8, 256>>>(ob, g2, o_w);

    gemm128<<<gOut, blk>>>(ob, Wo, out, TT, HIDN, PP);
}